// round 17
// baseline (speedup 1.0000x reference)
#include <cuda_runtime.h>

#define NCLASS 6
#define WARPS  32
#define THREADS (WARPS * 32)

__global__ void __launch_bounds__(THREADS)
se_loss_kernel(const float* __restrict__ se_pred,
               const int4* __restrict__ target,   // 4 x int32 per load
               float* __restrict__ out,
               int B, int nv /* int4 vectors per batch */)
{
    __shared__ float ssum[WARPS];

    const int lane = threadIdx.x & 31;
    const int w    = threadIdx.x >> 5;

    const int TILE = 64;                 // int4 per tile per batch (2 per lane)
    float acc = 0.0f;                    // this warp's BCE partial sum

    for (int b0 = 2 * w; b0 < B; b0 += 2 * WARPS) {
        const int b1 = b0 + 1;
        const int4* baseA = target + (size_t)b0 * nv;
        const int4* baseB = target + (size_t)b1 * nv;

        // se_pred for this pair: lanes 0-5 -> batch b0, lanes 6-11 -> batch b1
        float p = 0.5f;
        if (lane < 2 * NCLASS) {
            int b = b0 + (lane >= NCLASS);
            if (b < B) p = se_pred[b * NCLASS + (lane % NCLASS)];
        }

        // First tile of BOTH batches, loads issued together (latency overlap).
        int maskA = 0, maskB = 0;
        {
            int4 a0 = baseA[lane];
            int4 a1 = baseA[lane + 32];
            int4 c0, c1;
            if (b1 < B) { c0 = baseB[lane]; c1 = baseB[lane + 32]; }
            else        { c0 = make_int4(0,0,0,0); c1 = c0; }
            maskA = (1<<a0.x)|(1<<a0.y)|(1<<a0.z)|(1<<a0.w)
                  | (1<<a1.x)|(1<<a1.y)|(1<<a1.z)|(1<<a1.w);
            maskB = (1<<c0.x)|(1<<c0.y)|(1<<c0.z)|(1<<c0.w)
                  | (1<<c1.x)|(1<<c1.y)|(1<<c1.z)|(1<<c1.w);
        }
        maskA = __reduce_or_sync(0xffffffffu, maskA);
        maskB = __reduce_or_sync(0xffffffffu, maskB);

        // Fallback scans (astronomically rare for random labels; needed for
        // correctness when a class is truly absent).
        for (int i = TILE; maskA != 0x3F && i < nv; i += TILE) {
            int m = 0;
            int j = i + lane;
            if (j      < nv) { int4 v = baseA[j];      m |= (1<<v.x)|(1<<v.y)|(1<<v.z)|(1<<v.w); }
            if (j + 32 < nv) { int4 v = baseA[j + 32]; m |= (1<<v.x)|(1<<v.y)|(1<<v.z)|(1<<v.w); }
            maskA = __reduce_or_sync(0xffffffffu, maskA | m);
        }
        if (b1 < B) {
            for (int i = TILE; maskB != 0x3F && i < nv; i += TILE) {
                int m = 0;
                int j = i + lane;
                if (j      < nv) { int4 v = baseB[j];      m |= (1<<v.x)|(1<<v.y)|(1<<v.z)|(1<<v.w); }
                if (j + 32 < nv) { int4 v = baseB[j + 32]; m |= (1<<v.x)|(1<<v.y)|(1<<v.z)|(1<<v.w); }
                maskB = __reduce_or_sync(0xffffffffu, maskB | m);
            }
        }

        // BCE terms: lanes 0-5 use maskA, lanes 6-11 use maskB.
        if (lane < 2 * NCLASS && (b0 + (lane >= NCLASS)) < B) {
            int  c    = lane % NCLASS;
            int  mask = (lane < NCLASS) ? maskA : maskB;
            float t   = (float)((mask >> c) & 1);
            float lp  = fmaxf(logf(p),    -100.0f);
            float l1p = fmaxf(log1pf(-p), -100.0f);
            acc -= t * lp + (1.0f - t) * l1p;
        }
    }

    // Warp reduce, then block reduce via shared (fixed order -> deterministic).
    #pragma unroll
    for (int o = 16; o > 0; o >>= 1)
        acc += __shfl_down_sync(0xffffffffu, acc, o);
    if (lane == 0) ssum[w] = acc;
    __syncthreads();

    if (w == 0) {
        float s = (lane < WARPS) ? ssum[lane] : 0.0f;
        #pragma unroll
        for (int o = 16; o > 0; o >>= 1)
            s += __shfl_down_sync(0xffffffffu, s, o);
        if (lane == 0)
            out[0] = s / (float)(B * NCLASS);
    }
}

extern "C" void kernel_launch(void* const* d_in, const int* in_sizes, int n_in,
                              void* d_out, int out_size)
{
    const float* se_pred = (const float*)d_in[0];   // [B, 6] f32
    const int4*  target  = (const int4*)d_in[1];    // [B, H, W] int32

    int B = in_sizes[0] / NCLASS;                   // 64
    long long n_i32 = (long long)in_sizes[1];       // B*H*W int32 elements
    int nv = (int)(n_i32 / B / 4);                  // int4 vectors per batch

    se_loss_kernel<<<1, THREADS>>>(se_pred, target, (float*)d_out, B, nv);
}